// round 14
// baseline (speedup 1.0000x reference)
#include <cuda_runtime.h>
#include <cuda_fp16.h>
#include <math.h>
#include <cstdint>

// Problem constants
#define Bq   4
#define Tq   1024
#define Dq   1024
#define Hq   16
#define DHq  64
#define Mrows (Bq*Tq)
#define OUT_ELEMS ((size_t)Mrows*Dq)

// ---------------- device scratch (no runtime allocation) -------------------
__device__ __half g_lnq16[Mrows*Dq], g_lnk16[Mrows*Dq], g_lnv16[Mrows*Dq];
__device__ __half g_rp16 [Mrows*Dq];
__device__ __half g_q16  [Mrows*Dq], g_kr16 [Mrows*Dq], g_v16 [Mrows*Dq];
__device__ __half g_ctx16[Mrows*Dq];
__device__ __half g_wq16[Dq*Dq], g_wk16[Dq*Dq], g_wv16[Dq*Dq];
__device__ __half g_wr16[Dq*Dq], g_wo16[Dq*Dq];

// ------------------------- asm helpers -------------------------------------
__device__ __forceinline__ uint32_t smem_u32(const void* p) {
    uint32_t a;
    asm("{ .reg .u64 t; cvta.to.shared.u64 t, %1; cvt.u32.u64 %0, t; }"
        : "=r"(a) : "l"(p));
    return a;
}
__device__ __forceinline__ void cpa16(uint32_t s, const void* g) {
    asm volatile("cp.async.cg.shared.global [%0], [%1], 16;" :: "r"(s), "l"(g));
}
#define CPA_COMMIT() asm volatile("cp.async.commit_group;" ::: "memory")
#define CPA_WAIT(n)  asm volatile("cp.async.wait_group %0;" :: "n"(n) : "memory")

#define LDSM_X4(r0, r1, r2, r3, addr)                                        \
    asm volatile("ldmatrix.sync.aligned.m8n8.x4.shared.b16 {%0,%1,%2,%3}, [%4];" \
        : "=r"(r0), "=r"(r1), "=r"(r2), "=r"(r3) : "r"(addr))
#define LDSM_T_X4(r0, r1, r2, r3, addr)                                      \
    asm volatile("ldmatrix.sync.aligned.m8n8.x4.trans.shared.b16 {%0,%1,%2,%3}, [%4];" \
        : "=r"(r0), "=r"(r1), "=r"(r2), "=r"(r3) : "r"(addr))
#define MMA16816F16(c, a, b)                                                 \
    asm volatile("mma.sync.aligned.m16n8k16.row.col.f32.f16.f16.f32 "        \
        "{%0,%1,%2,%3}, {%4,%5,%6,%7}, {%8,%9}, {%0,%1,%2,%3};"              \
        : "+f"((c)[0]), "+f"((c)[1]), "+f"((c)[2]), "+f"((c)[3])             \
        : "r"((a)[0]), "r"((a)[1]), "r"((a)[2]), "r"((a)[3]),                \
          "r"((b)[0]), "r"((b)[1]))

__device__ __forceinline__ uint32_t h2x(float lo, float hi) {
    __half2 h = __floats2half2_rn(lo, hi);
    return *(uint32_t*)&h;
}

// ---------------------------------------------------------------------------
// 3x LayerNorm in one launch; fp16 output.
// ---------------------------------------------------------------------------
struct LnArgs {
    const float *x[3], *g[3], *b[3];
    __half* o[3];
};
__global__ __launch_bounds__(256)
void ln3_kernel(LnArgs a)
{
    int which = blockIdx.y;
    int row = blockIdx.x;
    int tid = threadIdx.x;
    const float4* xr = reinterpret_cast<const float4*>(a.x[which] + (size_t)row * Dq);
    float4 v = xr[tid];
    float s  = v.x + v.y + v.z + v.w;
    float s2 = v.x*v.x + v.y*v.y + v.z*v.z + v.w*v.w;
    #pragma unroll
    for (int o = 16; o; o >>= 1) {
        s  += __shfl_xor_sync(0xffffffffu, s,  o);
        s2 += __shfl_xor_sync(0xffffffffu, s2, o);
    }
    __shared__ float ws[8], ws2[8], stats[2];
    int w = tid >> 5, lane = tid & 31;
    if (lane == 0) { ws[w] = s; ws2[w] = s2; }
    __syncthreads();
    if (tid == 0) {
        float ts = 0.f, ts2 = 0.f;
        #pragma unroll
        for (int i = 0; i < 8; i++) { ts += ws[i]; ts2 += ws2[i]; }
        float mu  = ts * (1.0f / Dq);
        float var = ts2 * (1.0f / Dq) - mu * mu;
        stats[0] = mu;
        stats[1] = rsqrtf(var + 1e-5f);
    }
    __syncthreads();
    float mu = stats[0], rstd = stats[1];
    float4 g4 = reinterpret_cast<const float4*>(a.g[which])[tid];
    float4 b4 = reinterpret_cast<const float4*>(a.b[which])[tid];
    float o0 = (v.x - mu) * rstd * g4.x + b4.x;
    float o1 = (v.y - mu) * rstd * g4.y + b4.y;
    float o2 = (v.z - mu) * rstd * g4.z + b4.z;
    float o3 = (v.w - mu) * rstd * g4.w + b4.w;
    *(uint2*)&a.o[which][(size_t)row * Dq + tid*4] =
        make_uint2(h2x(o0, o1), h2x(o2, o3));
}

// fp32 -> fp16 (rel_pos)
__global__ __launch_bounds__(256)
void f16cvt_kernel(const float* __restrict__ x, __half* __restrict__ o)
{
    size_t i = ((size_t)blockIdx.x * 256 + threadIdx.x) * 4;
    float4 v = *(const float4*)&x[i];
    *(uint2*)&o[i] = make_uint2(h2x(v.x, v.y), h2x(v.z, v.w));
}

// 5 weights: W [K,N] -> WT [N,K] fp16 (per-weight scale)
struct WSplitArgs {
    const float* W[5];
    __half* H[5];
    float scale[5];
};
__global__ __launch_bounds__(256)
void wsplit5_kernel(WSplitArgs a)
{
    __shared__ float t[32][33];
    int z = blockIdx.z;
    const float* W = a.W[z];
    int tx = threadIdx.x & 31, ty = threadIdx.x >> 5;
    int nb = blockIdx.x * 32, kb = blockIdx.y * 32;
    #pragma unroll
    for (int i = 0; i < 32; i += 8)
        t[ty+i][tx] = W[(size_t)(kb + ty + i) * Dq + nb + tx];
    __syncthreads();
    float sc = a.scale[z];
    #pragma unroll
    for (int i = 0; i < 32; i += 8) {
        size_t off = (size_t)(nb + ty + i) * Dq + kb + tx;
        a.H[z][off] = __float2half_rn(t[tx][ty+i] * sc);
    }
}

// ---------------------------------------------------------------------------
// Shared GEMM tile constants
// ---------------------------------------------------------------------------
#define GROW 72
#define GT   (128*GROW)
#define TILEB (GT*2)                  // 18432 B per tile
#define G16_BYTES (4*TILEB)           // 2 buf x 2 tiles = 73728 -> 2 CTAs/SM

// ---------------------------------------------------------------------------
// Merged fp16 projection GEMM: q (16 chunks), v (16), kr=[lnk|rp]@[Wk;.1Wr](32)
// blockIdx.y: 0-31 -> q, 32-63 -> v, 64-95 -> kr. fp16 output.
// 256 threads, 8 warps (4m x 2n), warp tile 32x64, 2 CTAs/SM.
// ---------------------------------------------------------------------------
struct Proj16Args {
    const __half *A[3], *B[3];
    const __half *A2, *B2;
    const float* bias[3];
    float alpha[3];
    __half* C[3];
    int nch[3];
};

__global__ __launch_bounds__(256, 2)
void proj16_kernel(Proj16Args a)
{
    extern __shared__ __half gsm[];
    const uint32_t sb = smem_u32(gsm);

    const int g  = blockIdx.y >> 5;
    const int bm = (blockIdx.y & 31) * 128, bn = blockIdx.x * 128;

    const int tid  = threadIdx.x;
    const int wid  = tid >> 5, lane = tid & 31;
    const int wm   = wid & 3,  wn   = wid >> 2;      // 4x2 warps, 32x64 tiles
    const int g_row = (lane & 7) + ((lane >> 3) & 1) * 8;
    const int g_col = ((lane >> 4) & 1) * 8;
    const int lrow0 = tid >> 3, lc16 = tid & 7;

    const __half *A1 = a.A[g], *B1 = a.B[g];
    const int nchunks = a.nch[g];

    float acc[2][8][4];
    #pragma unroll
    for (int mt = 0; mt < 2; mt++)
        #pragma unroll
        for (int nf = 0; nf < 8; nf++)
            #pragma unroll
            for (int r = 0; r < 4; r++) acc[mt][nf][r] = 0.f;

    auto load_chunk = [&](int buf, int kc) {
        const __half *pA, *pB;
        int k0;
        if (kc < 16) { pA = A1;   pB = B1;   k0 = kc * 64; }
        else         { pA = a.A2; pB = a.B2; k0 = (kc - 16) * 64; }
        uint32_t base = sb + buf * 2 * TILEB;
        #pragma unroll
        for (int i = 0; i < 4; i++) {
            int row = lrow0 + i * 32;
            uint32_t so = (uint32_t)((row * GROW + lc16 * 8) * 2);
            cpa16(base + 0*TILEB + so, pA + (size_t)(bm + row) * Dq + k0 + lc16 * 8);
            cpa16(base + 1*TILEB + so, pB + (size_t)(bn + row) * Dq + k0 + lc16 * 8);
        }
        CPA_COMMIT();
    };

    load_chunk(0, 0);

    for (int kc = 0; kc < nchunks; kc++) {
        CPA_WAIT(0);
        __syncthreads();
        if (kc + 1 < nchunks) load_chunk((kc + 1) & 1, kc + 1);

        uint32_t base = sb + (kc & 1) * 2 * TILEB;
        uint32_t uA = base, uB = base + TILEB;

        #pragma unroll
        for (int ks = 0; ks < 4; ks++) {
            const int kcol = ks * 16 + g_col;
            uint32_t av[2][4];
            #pragma unroll
            for (int mt = 0; mt < 2; mt++) {
                uint32_t off = ((wm*32 + mt*16 + g_row) * GROW + kcol) * 2;
                LDSM_X4(av[mt][0], av[mt][1], av[mt][2], av[mt][3], uA + off);
            }
            uint32_t bv[8][2];
            #pragma unroll
            for (int np = 0; np < 4; np++) {
                uint32_t off = ((wn*64 + np*16 + g_row) * GROW + kcol) * 2;
                uint32_t r0, r1, r2, r3;
                LDSM_X4(r0, r1, r2, r3, uB + off);
                bv[2*np][0] = r0;   bv[2*np][1] = r2;
                bv[2*np+1][0] = r1; bv[2*np+1][1] = r3;
            }
            #pragma unroll
            for (int mt = 0; mt < 2; mt++)
                #pragma unroll
                for (int nf = 0; nf < 8; nf++)
                    MMA16816F16(acc[mt][nf], av[mt], bv[nf]);
        }
    }

    const float alpha = a.alpha[g];
    const float* bias = a.bias[g];
    __half* C = a.C[g];
    const int qrow = lane >> 2, qcol = (lane & 3) * 2;
    #pragma unroll
    for (int mt = 0; mt < 2; mt++) {
        int r0 = bm + wm*32 + mt*16 + qrow;
        #pragma unroll
        for (int nf = 0; nf < 8; nf++) {
            int col = bn + wn*64 + nf*8 + qcol;
            float2 vb = *(const float2*)&bias[col];
            size_t off0 = (size_t)r0 * Dq + col;
            size_t off1 = (size_t)(r0 + 8) * Dq + col;
            *(uint32_t*)&C[off0] = h2x(alpha * (acc[mt][nf][0] + vb.x),
                                       alpha * (acc[mt][nf][1] + vb.y));
            *(uint32_t*)&C[off1] = h2x(alpha * (acc[mt][nf][2] + vb.x),
                                       alpha * (acc[mt][nf][3] + vb.y));
        }
    }
}

// ---------------------------------------------------------------------------
// fp16 GEMM, fp32 output: out = ctx@Wo^T + bias. Same 256-thread shape.
// ---------------------------------------------------------------------------
__global__ __launch_bounds__(256, 2)
void gemm16_out_kernel(const __half* __restrict__ A, const __half* __restrict__ B,
                       const float* __restrict__ bias, float* __restrict__ C)
{
    extern __shared__ __half gsm[];
    const uint32_t sb = smem_u32(gsm);

    const int tid  = threadIdx.x;
    const int wid  = tid >> 5, lane = tid & 31;
    const int wm   = wid & 3,  wn   = wid >> 2;
    const int bm = blockIdx.y * 128, bn = blockIdx.x * 128;
    const int g_row = (lane & 7) + ((lane >> 3) & 1) * 8;
    const int g_col = ((lane >> 4) & 1) * 8;
    const int lrow0 = tid >> 3, lc16 = tid & 7;

    float acc[2][8][4];
    #pragma unroll
    for (int mt = 0; mt < 2; mt++)
        #pragma unroll
        for (int nf = 0; nf < 8; nf++)
            #pragma unroll
            for (int r = 0; r < 4; r++) acc[mt][nf][r] = 0.f;

    auto load_chunk = [&](int buf, int k0) {
        uint32_t base = sb + buf * 2 * TILEB;
        #pragma unroll
        for (int i = 0; i < 4; i++) {
            int row = lrow0 + i * 32;
            uint32_t so = (uint32_t)((row * GROW + lc16 * 8) * 2);
            cpa16(base + 0*TILEB + so, A + (size_t)(bm + row) * Dq + k0 + lc16 * 8);
            cpa16(base + 1*TILEB + so, B + (size_t)(bn + row) * Dq + k0 + lc16 * 8);
        }
        CPA_COMMIT();
    };

    load_chunk(0, 0);
    for (int kc = 0; kc < 16; kc++) {
        CPA_WAIT(0);
        __syncthreads();
        if (kc + 1 < 16) load_chunk((kc + 1) & 1, (kc + 1) * 64);

        uint32_t base = sb + (kc & 1) * 2 * TILEB;
        uint32_t uA = base, uB = base + TILEB;

        #pragma unroll
        for (int ks = 0; ks < 4; ks++) {
            const int kcol = ks * 16 + g_col;
            uint32_t av[2][4];
            #pragma unroll
            for (int mt = 0; mt < 2; mt++) {
                uint32_t off = ((wm*32 + mt*16 + g_row) * GROW + kcol) * 2;
                LDSM_X4(av[mt][0], av[mt][1], av[mt][2], av[mt][3], uA + off);
            }
            uint32_t bv[8][2];
            #pragma unroll
            for (int np = 0; np < 4; np++) {
                uint32_t off = ((wn*64 + np*16 + g_row) * GROW + kcol) * 2;
                uint32_t r0, r1, r2, r3;
                LDSM_X4(r0, r1, r2, r3, uB + off);
                bv[2*np][0] = r0;   bv[2*np][1] = r2;
                bv[2*np+1][0] = r1; bv[2*np+1][1] = r3;
            }
            #pragma unroll
            for (int mt = 0; mt < 2; mt++)
                #pragma unroll
                for (int nf = 0; nf < 8; nf++)
                    MMA16816F16(acc[mt][nf], av[mt], bv[nf]);
        }
    }

    const int qrow = lane >> 2, qcol = (lane & 3) * 2;
    #pragma unroll
    for (int mt = 0; mt < 2; mt++) {
        int r0 = bm + wm*32 + mt*16 + qrow;
        #pragma unroll
        for (int nf = 0; nf < 8; nf++) {
            int col = bn + wn*64 + nf*8 + qcol;
            float2 vb = *(const float2*)&bias[col];
            size_t off0 = (size_t)r0 * Dq + col;
            size_t off1 = (size_t)(r0 + 8) * Dq + col;
            *(float2*)&C[off0] = make_float2(acc[mt][nf][0] + vb.x, acc[mt][nf][1] + vb.y);
            *(float2*)&C[off1] = make_float2(acc[mt][nf][2] + vb.x, acc[mt][nf][3] + vb.y);
        }
    }
}

// ---------------------------------------------------------------------------
// Attention v9: single-pass flash, all-fp16 operands, fp32 accum.
// Stores UNNORMALIZED p = exp(s - m_chunk) to probs during the loop (values
// already computed for the PV fragments), remembers per-chunk running max
// mh[st]; final pass is a pure multiply by exp(mh[st]-M)*iL (no exp per elem).
// smem tiles: 0 q, 1 k0, 2 v0, 3 k1, 4 v1 (+ mask)
// ---------------------------------------------------------------------------
#define ATS 72
#define ATILEB (128*ATS*2)
#define ATTN_SMEM (5*ATILEB + Tq*4)   // 96256

__global__ __launch_bounds__(256, 1)
void attn9_kernel(const __half* __restrict__ q_g, const __half* __restrict__ k_g,
                  const __half* __restrict__ v_g,
                  const int* __restrict__ mask, float* __restrict__ probs,
                  __half* __restrict__ ctx16)
{
    extern __shared__ __half sm_[];
    const uint32_t sb = smem_u32(sm_);
    int* msk = (int*)(sm_ + 5*128*ATS);

    const int t0 = blockIdx.x * 128, h = blockIdx.y, b = blockIdx.z;
    const int tid = threadIdx.x, wid = tid >> 5, lane = tid & 31;
    const int qrow = lane >> 2, qc2 = (lane & 3) * 2;
    const int g_row = (lane & 7) + ((lane >> 3) & 1) * 8;
    const int g_col = ((lane >> 4) & 1) * 8;
    const int lrow0 = tid >> 3, lc16 = tid & 7;

    const size_t gq  = ((size_t)(b*Tq + t0)) * Dq + h*DHq;
    const size_t gkv = ((size_t)(b*Tq)) * Dq + h*DHq;

    auto load_t = [&](int tile, const __half* src, size_t gbase) {
        #pragma unroll
        for (int i = 0; i < 4; i++) {
            int row = lrow0 + i*32;
            uint32_t so = (uint32_t)((row*ATS + lc16*8) * 2);
            cpa16(sb + tile*ATILEB + so, src + gbase + (size_t)row * Dq + lc16*8);
        }
    };

    load_t(0, q_g, gq);
    load_t(1, k_g, gkv);
    CPA_COMMIT();
    load_t(2, v_g, gkv);
    CPA_COMMIT();
    for (int s = tid; s < Tq; s += 256) msk[s] = mask[b*Tq + s];

    float m0 = -1e30f, m1 = -1e30f, l0 = 0.f, l1 = 0.f;
    float mh0[8], mh1[8];
    float cacc[8][4];
    #pragma unroll
    for (int nf = 0; nf < 8; nf++) {
        cacc[nf][0] = 0.f; cacc[nf][1] = 0.f; cacc[nf][2] = 0.f; cacc[nf][3] = 0.f;
    }

    const size_t prow0 = ((size_t)((b*Hq + h)*Tq) + t0 + wid*16 + qrow) * Tq;
    const uint32_t uq = sb;

    #pragma unroll
    for (int st = 0; st < 8; st++) {
        const int kb_ = 1 + (st & 1) * 2;
        const int vb_ = 2 + (st & 1) * 2;

        CPA_WAIT(1);
        __syncthreads();

        if (st < 7) {
            const int nk = 1 + ((st+1) & 1) * 2;
            const int nv = 2 + ((st+1) & 1) * 2;
            load_t(nk, k_g, gkv + (size_t)((st+1)*128) * Dq);
            CPA_COMMIT();
            load_t(nv, v_g, gkv + (size_t)((st+1)*128) * Dq);
            CPA_COMMIT();
        }

        // ---- S = q @ k^T : single-term fp16 ----
        float acc[16][4];
        #pragma unroll
        for (int nf = 0; nf < 16; nf++) {
            acc[nf][0] = 0.f; acc[nf][1] = 0.f; acc[nf][2] = 0.f; acc[nf][3] = 0.f;
        }
        {
            uint32_t uk = sb + kb_*ATILEB;
            #pragma unroll
            for (int ks = 0; ks < 4; ks++) {
                uint32_t aq[4];
                uint32_t aoff = (uint32_t)(((wid*16 + g_row) * ATS + ks*16 + g_col) * 2);
                LDSM_X4(aq[0], aq[1], aq[2], aq[3], uq + aoff);
                #pragma unroll
                for (int np = 0; np < 8; np++) {
                    uint32_t boff = (uint32_t)(((np*16 + g_row) * ATS + ks*16 + g_col) * 2);
                    uint32_t r0, r1, r2, r3;
                    LDSM_X4(r0, r1, r2, r3, uk + boff);
                    uint32_t b0[2] = {r0, r2}, b1[2] = {r1, r3};
                    MMA16816F16(acc[2*np],   aq, b0);
                    MMA16816F16(acc[2*np+1], aq, b1);
                }
            }
        }

        // ---- mask + online max ----
        int s0 = st * 128;
        float cm0 = -1e30f, cm1 = -1e30f;
        #pragma unroll
        for (int nf = 0; nf < 16; nf++) {
            int col = s0 + nf*8 + qc2;
            int k0 = msk[col], k1 = msk[col + 1];
            acc[nf][0] = k0 ? acc[nf][0] : -1e9f;
            acc[nf][1] = k1 ? acc[nf][1] : -1e9f;
            acc[nf][2] = k0 ? acc[nf][2] : -1e9f;
            acc[nf][3] = k1 ? acc[nf][3] : -1e9f;
            cm0 = fmaxf(cm0, fmaxf(acc[nf][0], acc[nf][1]));
            cm1 = fmaxf(cm1, fmaxf(acc[nf][2], acc[nf][3]));
        }
        cm0 = fmaxf(cm0, __shfl_xor_sync(0xffffffffu, cm0, 1));
        cm0 = fmaxf(cm0, __shfl_xor_sync(0xffffffffu, cm0, 2));
        cm1 = fmaxf(cm1, __shfl_xor_sync(0xffffffffu, cm1, 1));
        cm1 = fmaxf(cm1, __shfl_xor_sync(0xffffffffu, cm1, 2));
        float nm0 = fmaxf(m0, cm0), nm1 = fmaxf(m1, cm1);
        mh0[st] = nm0;  mh1[st] = nm1;
        float r0 = __expf(m0 - nm0), r1 = __expf(m1 - nm1);
        #pragma unroll
        for (int nf = 0; nf < 8; nf++) {
            cacc[nf][0] *= r0; cacc[nf][1] *= r0;
            cacc[nf][2] *= r1; cacc[nf][3] *= r1;
        }

        // ---- p = exp(s - nm): store unnormalized p + build fp16 P frags ----
        float sa0 = 0.f, sa1 = 0.f;
        uint32_t aP[8][4];
        #pragma unroll
        for (int j = 0; j < 8; j++) {
            float p[8];
            #pragma unroll
            for (int u = 0; u < 2; u++) {
                int nf = 2*j + u;
                int col = s0 + nf*8 + qc2;
                float p0 = __expf(acc[nf][0] - nm0);
                float p1 = __expf(acc[nf][1] - nm0);
                float p2 = __expf(acc[nf][2] - nm1);
                float p3 = __expf(acc[nf][3] - nm1);
                *(float2*)&probs[prow0 + col]        = make_float2(p0, p1);
                *(float2*)&probs[prow0 + 8*Tq + col] = make_float2(p2, p3);
                sa0 += p0 + p1;  sa1 += p2 + p3;
                p[u*4+0] = p0; p[u*4+1] = p1; p[u*4+2] = p2; p[u*4+3] = p3;
            }
            aP[j][0] = h2x(p[0], p[1]);
            aP[j][1] = h2x(p[2], p[3]);
            aP[j][2] = h2x(p[4], p[5]);
            aP[j][3] = h2x(p[6], p[7]);
        }
        sa0 += __shfl_xor_sync(0xffffffffu, sa0, 1);
        sa0 += __shfl_xor_sync(0xffffffffu, sa0, 2);
        sa1 += __shfl_xor_sync(0xffffffffu, sa1, 1);
        sa1 += __shfl_xor_sync(0xffffffffu, sa1, 2);
        l0 = l0 * r0 + sa0;  m0 = nm0;
        l1 = l1 * r1 + sa1;  m1 = nm1;

        if (st < 7) { CPA_WAIT(2); } else { CPA_WAIT(0); }
        __syncthreads();

        // ---- ctx += P @ V (fp16) ----
        uint32_t uv = sb + vb_*ATILEB;
        #pragma unroll
        for (int ks = 0; ks < 8; ks++) {
            uint32_t bv[8][2];
            #pragma unroll
            for (int npv = 0; npv < 4; npv++) {
                uint32_t off = (uint32_t)(((ks*16 + g_row) * ATS + npv*16 + g_col) * 2);
                uint32_t r0v, r1v, r2v, r3v;
                LDSM_T_X4(r0v, r1v, r2v, r3v, uv + off);
                bv[2*npv][0] = r0v;   bv[2*npv][1] = r1v;
                bv[2*npv+1][0] = r2v; bv[2*npv+1][1] = r3v;
            }
            #pragma unroll
            for (int nf = 0; nf < 8; nf++)
                MMA16816F16(cacc[nf], aP[ks], bv[nf]);
        }
    }

    const float iL0 = 1.0f / l0, iL1 = 1.0f / l1;

    // final pass: pure multiply p *= exp(mh[st]-M)*iL (2 exps per chunk)
    #pragma unroll
    for (int st = 0; st < 8; st++) {
        float sc0 = __expf(mh0[st] - m0) * iL0;
        float sc1 = __expf(mh1[st] - m1) * iL1;
        int s0 = st * 128;
        #pragma unroll
        for (int nf = 0; nf < 16; nf++) {
            int col = s0 + nf*8 + qc2;
            float2 v0 = *(float2*)&probs[prow0 + col];
            float2 v1 = *(float2*)&probs[prow0 + 8*Tq + col];
            v0.x *= sc0; v0.y *= sc0;
            v1.x *= sc1; v1.y *= sc1;
            *(float2*)&probs[prow0 + col]        = v0;
            *(float2*)&probs[prow0 + 8*Tq + col] = v1;
        }
    }

    // write ctx fp16
    {
        int r = t0 + wid*16 + qrow;
        size_t base0 = ((size_t)(b*Tq + r)) * Dq + h*DHq;
        size_t base1 = ((size_t)(b*Tq + r + 8)) * Dq + h*DHq;
        #pragma unroll
        for (int nf = 0; nf < 8; nf++) {
            int col = nf*8 + qc2;
            *(uint32_t*)&ctx16[base0 + col] = h2x(cacc[nf][0] * iL0, cacc[nf][1] * iL0);
            *(uint32_t*)&ctx16[base1 + col] = h2x(cacc[nf][2] * iL1, cacc[nf][3] * iL1);
        }
    }
}

// ---------------------------------------------------------------------------
extern "C" void kernel_launch(void* const* d_in, const int* in_sizes, int n_in,
                              void* d_out, int out_size)
{
    const float* query   = (const float*)d_in[0];
    const float* key     = (const float*)d_in[1];
    const float* value   = (const float*)d_in[2];
    const float* rel_pos = (const float*)d_in[3];
    const int*   kpm     = (const int*)  d_in[4];
    const float* qn_g = (const float*)d_in[5];
    const float* qn_b = (const float*)d_in[6];
    const float* kn_g = (const float*)d_in[7];
    const float* kn_b = (const float*)d_in[8];
    const float* vn_g = (const float*)d_in[9];
    const float* vn_b = (const float*)d_in[10];
    const float* Wq = (const float*)d_in[11];
    const float* bq = (const float*)d_in[12];
    const float* Wk = (const float*)d_in[13];
    const float* bk = (const float*)d_in[14];
    const float* Wv = (const float*)d_in[15];
    const float* bv = (const float*)d_in[16];
    const float* Wr = (const float*)d_in[17];
    const float* Wo = (const float*)d_in[18];
    const float* bo = (const float*)d_in[19];

    float* out   = (float*)d_out;
    float* probs = out + OUT_ELEMS;

    __half *lnq16,*lnk16,*lnv16,*rp16,*q16,*kr16,*v16,*ctx16;
    __half *wq16,*wk16,*wv16,*wr16,*wo16;
    cudaGetSymbolAddress((void**)&lnq16, g_lnq16);
    cudaGetSymbolAddress((void**)&lnk16, g_lnk16);
    cudaGetSymbolAddress((void**)&lnv16, g_lnv16);
    cudaGetSymbolAddress((void**)&rp16,  g_rp16);
    cudaGetSymbolAddress((void**)&q16,   g_q16);
    cudaGetSymbolAddress((void**)&kr16,  g_kr16);
    cudaGetSymbolAddress((void**)&v16,   g_v16);
    cudaGetSymbolAddress((void**)&ctx16, g_ctx16);
    cudaGetSymbolAddress((void**)&wq16, g_wq16);
    cudaGetSymbolAddress((void**)&wk16, g_wk16);
    cudaGetSymbolAddress((void**)&wv16, g_wv16);
    cudaGetSymbolAddress((void**)&wr16, g_wr16);
    cudaGetSymbolAddress((void**)&wo16, g_wo16);

    cudaFuncSetAttribute(proj16_kernel, cudaFuncAttributeMaxDynamicSharedMemorySize, G16_BYTES);
    cudaFuncSetAttribute(gemm16_out_kernel, cudaFuncAttributeMaxDynamicSharedMemorySize, G16_BYTES);
    cudaFuncSetAttribute(attn9_kernel, cudaFuncAttributeMaxDynamicSharedMemorySize, ATTN_SMEM);

    // 1) weight transpose -> fp16 (0.1 folded into Wr)
    WSplitArgs wa;
    wa.W[0]=Wq; wa.H[0]=wq16; wa.scale[0]=1.f;
    wa.W[1]=Wk; wa.H[1]=wk16; wa.scale[1]=1.f;
    wa.W[2]=Wv; wa.H[2]=wv16; wa.scale[2]=1.f;
    wa.W[3]=Wr; wa.H[3]=wr16; wa.scale[3]=0.1f;
    wa.W[4]=Wo; wa.H[4]=wo16; wa.scale[4]=1.f;
    dim3 wgrid(Dq/32, Dq/32, 5);
    wsplit5_kernel<<<wgrid, 256>>>(wa);

    // 2) LayerNorms -> fp16, rel_pos -> fp16
    LnArgs la;
    la.x[0]=query; la.g[0]=qn_g; la.b[0]=qn_b; la.o[0]=lnq16;
    la.x[1]=key;   la.g[1]=kn_g; la.b[1]=kn_b; la.o[1]=lnk16;
    la.x[2]=value; la.g[2]=vn_g; la.b[2]=vn_b; la.o[2]=lnv16;
    ln3_kernel<<<dim3(Mrows, 3), 256>>>(la);
    f16cvt_kernel<<<(Mrows*Dq)/1024, 256>>>(rel_pos, rp16);

    // 3) merged fp16 projections: q, v, kr=[lnk|rp]@[Wk;0.1Wr]
    Proj16Args pa;
    pa.A[0]=lnq16; pa.B[0]=wq16; pa.bias[0]=bq; pa.alpha[0]=0.125f;
    pa.C[0]=q16;  pa.nch[0]=16;
    pa.A[1]=lnv16; pa.B[1]=wv16; pa.bias[1]=bv; pa.alpha[1]=1.f;
    pa.C[1]=v16;  pa.nch[1]=16;
    pa.A[2]=lnk16; pa.B[2]=wk16; pa.bias[2]=bk; pa.alpha[2]=1.f;
    pa.A2=rp16; pa.B2=wr16;
    pa.C[2]=kr16; pa.nch[2]=32;
    proj16_kernel<<<dim3(Dq/128, 96), 256, G16_BYTES>>>(pa);

    // 4) single-pass flash attention -> unnormalized p + final rescale + ctx
    dim3 agrid(Tq/128, Hq, Bq);
    attn9_kernel<<<agrid, 256, ATTN_SMEM>>>(q16, kr16, v16, kpm, probs, ctx16);

    // 5) out = ctx@Wo + bo
    gemm16_out_kernel<<<dim3(Dq/128, Mrows/128), 256, G16_BYTES>>>(
        ctx16, wo16, bo, out);
}

// round 15
// speedup vs baseline: 1.5451x; 1.5451x over previous
#include <cuda_runtime.h>
#include <cuda_fp16.h>
#include <math.h>
#include <cstdint>

// Problem constants
#define Bq   4
#define Tq   1024
#define Dq   1024
#define Hq   16
#define DHq  64
#define Mrows (Bq*Tq)
#define OUT_ELEMS ((size_t)Mrows*Dq)

// ---------------- device scratch (no runtime allocation) -------------------
__device__ __half g_lnq16[Mrows*Dq], g_lnk16[Mrows*Dq], g_lnv16[Mrows*Dq];
__device__ __half g_rp16 [Mrows*Dq];
__device__ __half g_q16  [Mrows*Dq], g_kr16 [Mrows*Dq], g_v16 [Mrows*Dq];
__device__ __half g_ctx16[Mrows*Dq];
__device__ __half g_wq16[Dq*Dq], g_wk16[Dq*Dq], g_wv16[Dq*Dq];
__device__ __half g_wr16[Dq*Dq], g_wo16[Dq*Dq];

// ------------------------- asm helpers -------------------------------------
__device__ __forceinline__ uint32_t smem_u32(const void* p) {
    uint32_t a;
    asm("{ .reg .u64 t; cvta.to.shared.u64 t, %1; cvt.u32.u64 %0, t; }"
        : "=r"(a) : "l"(p));
    return a;
}
__device__ __forceinline__ void cpa16(uint32_t s, const void* g) {
    asm volatile("cp.async.cg.shared.global [%0], [%1], 16;" :: "r"(s), "l"(g));
}
#define CPA_COMMIT() asm volatile("cp.async.commit_group;" ::: "memory")
#define CPA_WAIT(n)  asm volatile("cp.async.wait_group %0;" :: "n"(n) : "memory")

#define LDSM_X4(r0, r1, r2, r3, addr)                                        \
    asm volatile("ldmatrix.sync.aligned.m8n8.x4.shared.b16 {%0,%1,%2,%3}, [%4];" \
        : "=r"(r0), "=r"(r1), "=r"(r2), "=r"(r3) : "r"(addr))
#define LDSM_T_X4(r0, r1, r2, r3, addr)                                      \
    asm volatile("ldmatrix.sync.aligned.m8n8.x4.trans.shared.b16 {%0,%1,%2,%3}, [%4];" \
        : "=r"(r0), "=r"(r1), "=r"(r2), "=r"(r3) : "r"(addr))
#define MMA16816F16(c, a, b)                                                 \
    asm volatile("mma.sync.aligned.m16n8k16.row.col.f32.f16.f16.f32 "        \
        "{%0,%1,%2,%3}, {%4,%5,%6,%7}, {%8,%9}, {%0,%1,%2,%3};"              \
        : "+f"((c)[0]), "+f"((c)[1]), "+f"((c)[2]), "+f"((c)[3])             \
        : "r"((a)[0]), "r"((a)[1]), "r"((a)[2]), "r"((a)[3]),                \
          "r"((b)[0]), "r"((b)[1]))

__device__ __forceinline__ uint32_t h2x(float lo, float hi) {
    __half2 h = __floats2half2_rn(lo, hi);
    return *(uint32_t*)&h;
}

// ---------------------------------------------------------------------------
// 3x LayerNorm in one launch; fp16 output.
// ---------------------------------------------------------------------------
struct LnArgs {
    const float *x[3], *g[3], *b[3];
    __half* o[3];
};
__global__ __launch_bounds__(256)
void ln3_kernel(LnArgs a)
{
    int which = blockIdx.y;
    int row = blockIdx.x;
    int tid = threadIdx.x;
    const float4* xr = reinterpret_cast<const float4*>(a.x[which] + (size_t)row * Dq);
    float4 v = xr[tid];
    float s  = v.x + v.y + v.z + v.w;
    float s2 = v.x*v.x + v.y*v.y + v.z*v.z + v.w*v.w;
    #pragma unroll
    for (int o = 16; o; o >>= 1) {
        s  += __shfl_xor_sync(0xffffffffu, s,  o);
        s2 += __shfl_xor_sync(0xffffffffu, s2, o);
    }
    __shared__ float ws[8], ws2[8], stats[2];
    int w = tid >> 5, lane = tid & 31;
    if (lane == 0) { ws[w] = s; ws2[w] = s2; }
    __syncthreads();
    if (tid == 0) {
        float ts = 0.f, ts2 = 0.f;
        #pragma unroll
        for (int i = 0; i < 8; i++) { ts += ws[i]; ts2 += ws2[i]; }
        float mu  = ts * (1.0f / Dq);
        float var = ts2 * (1.0f / Dq) - mu * mu;
        stats[0] = mu;
        stats[1] = rsqrtf(var + 1e-5f);
    }
    __syncthreads();
    float mu = stats[0], rstd = stats[1];
    float4 g4 = reinterpret_cast<const float4*>(a.g[which])[tid];
    float4 b4 = reinterpret_cast<const float4*>(a.b[which])[tid];
    float o0 = (v.x - mu) * rstd * g4.x + b4.x;
    float o1 = (v.y - mu) * rstd * g4.y + b4.y;
    float o2 = (v.z - mu) * rstd * g4.z + b4.z;
    float o3 = (v.w - mu) * rstd * g4.w + b4.w;
    *(uint2*)&a.o[which][(size_t)row * Dq + tid*4] =
        make_uint2(h2x(o0, o1), h2x(o2, o3));
}

// fp32 -> fp16 (rel_pos)
__global__ __launch_bounds__(256)
void f16cvt_kernel(const float* __restrict__ x, __half* __restrict__ o)
{
    size_t i = ((size_t)blockIdx.x * 256 + threadIdx.x) * 4;
    float4 v = *(const float4*)&x[i];
    *(uint2*)&o[i] = make_uint2(h2x(v.x, v.y), h2x(v.z, v.w));
}

// 5 weights: W [K,N] -> WT [N,K] fp16 (per-weight scale)
struct WSplitArgs {
    const float* W[5];
    __half* H[5];
    float scale[5];
};
__global__ __launch_bounds__(256)
void wsplit5_kernel(WSplitArgs a)
{
    __shared__ float t[32][33];
    int z = blockIdx.z;
    const float* W = a.W[z];
    int tx = threadIdx.x & 31, ty = threadIdx.x >> 5;
    int nb = blockIdx.x * 32, kb = blockIdx.y * 32;
    #pragma unroll
    for (int i = 0; i < 32; i += 8)
        t[ty+i][tx] = W[(size_t)(kb + ty + i) * Dq + nb + tx];
    __syncthreads();
    float sc = a.scale[z];
    #pragma unroll
    for (int i = 0; i < 32; i += 8) {
        size_t off = (size_t)(nb + ty + i) * Dq + kb + tx;
        a.H[z][off] = __float2half_rn(t[tx][ty+i] * sc);
    }
}

// ---------------------------------------------------------------------------
// Shared GEMM tile constants
// ---------------------------------------------------------------------------
#define GROW 72
#define GT   (128*GROW)
#define TILEB (GT*2)                  // 18432 B per tile
#define G16_BYTES (4*TILEB)           // 2 buf x 2 tiles = 73728 -> 2 CTAs/SM

// ---------------------------------------------------------------------------
// Merged fp16 projection GEMM: q (16 chunks), v (16), kr=[lnk|rp]@[Wk;.1Wr](32)
// blockIdx.y: 0-31 -> q, 32-63 -> v, 64-95 -> kr. fp16 output.
// 256 threads, 8 warps (4m x 2n), warp tile 32x64, 2 CTAs/SM.
// ---------------------------------------------------------------------------
struct Proj16Args {
    const __half *A[3], *B[3];
    const __half *A2, *B2;
    const float* bias[3];
    float alpha[3];
    __half* C[3];
    int nch[3];
};

__global__ __launch_bounds__(256, 2)
void proj16_kernel(Proj16Args a)
{
    extern __shared__ __half gsm[];
    const uint32_t sb = smem_u32(gsm);

    const int g  = blockIdx.y >> 5;
    const int bm = (blockIdx.y & 31) * 128, bn = blockIdx.x * 128;

    const int tid  = threadIdx.x;
    const int wid  = tid >> 5, lane = tid & 31;
    const int wm   = wid & 3,  wn   = wid >> 2;
    const int g_row = (lane & 7) + ((lane >> 3) & 1) * 8;
    const int g_col = ((lane >> 4) & 1) * 8;
    const int lrow0 = tid >> 3, lc16 = tid & 7;

    const __half *A1 = a.A[g], *B1 = a.B[g];
    const int nchunks = a.nch[g];

    float acc[2][8][4];
    #pragma unroll
    for (int mt = 0; mt < 2; mt++)
        #pragma unroll
        for (int nf = 0; nf < 8; nf++)
            #pragma unroll
            for (int r = 0; r < 4; r++) acc[mt][nf][r] = 0.f;

    auto load_chunk = [&](int buf, int kc) {
        const __half *pA, *pB;
        int k0;
        if (kc < 16) { pA = A1;   pB = B1;   k0 = kc * 64; }
        else         { pA = a.A2; pB = a.B2; k0 = (kc - 16) * 64; }
        uint32_t base = sb + buf * 2 * TILEB;
        #pragma unroll
        for (int i = 0; i < 4; i++) {
            int row = lrow0 + i * 32;
            uint32_t so = (uint32_t)((row * GROW + lc16 * 8) * 2);
            cpa16(base + 0*TILEB + so, pA + (size_t)(bm + row) * Dq + k0 + lc16 * 8);
            cpa16(base + 1*TILEB + so, pB + (size_t)(bn + row) * Dq + k0 + lc16 * 8);
        }
        CPA_COMMIT();
    };

    load_chunk(0, 0);

    for (int kc = 0; kc < nchunks; kc++) {
        CPA_WAIT(0);
        __syncthreads();
        if (kc + 1 < nchunks) load_chunk((kc + 1) & 1, kc + 1);

        uint32_t base = sb + (kc & 1) * 2 * TILEB;
        uint32_t uA = base, uB = base + TILEB;

        #pragma unroll
        for (int ks = 0; ks < 4; ks++) {
            const int kcol = ks * 16 + g_col;
            uint32_t av[2][4];
            #pragma unroll
            for (int mt = 0; mt < 2; mt++) {
                uint32_t off = ((wm*32 + mt*16 + g_row) * GROW + kcol) * 2;
                LDSM_X4(av[mt][0], av[mt][1], av[mt][2], av[mt][3], uA + off);
            }
            uint32_t bv[8][2];
            #pragma unroll
            for (int np = 0; np < 4; np++) {
                uint32_t off = ((wn*64 + np*16 + g_row) * GROW + kcol) * 2;
                uint32_t r0, r1, r2, r3;
                LDSM_X4(r0, r1, r2, r3, uB + off);
                bv[2*np][0] = r0;   bv[2*np][1] = r2;
                bv[2*np+1][0] = r1; bv[2*np+1][1] = r3;
            }
            #pragma unroll
            for (int mt = 0; mt < 2; mt++)
                #pragma unroll
                for (int nf = 0; nf < 8; nf++)
                    MMA16816F16(acc[mt][nf], av[mt], bv[nf]);
        }
    }

    const float alpha = a.alpha[g];
    const float* bias = a.bias[g];
    __half* C = a.C[g];
    const int qrow = lane >> 2, qcol = (lane & 3) * 2;
    #pragma unroll
    for (int mt = 0; mt < 2; mt++) {
        int r0 = bm + wm*32 + mt*16 + qrow;
        #pragma unroll
        for (int nf = 0; nf < 8; nf++) {
            int col = bn + wn*64 + nf*8 + qcol;
            float2 vb = *(const float2*)&bias[col];
            size_t off0 = (size_t)r0 * Dq + col;
            size_t off1 = (size_t)(r0 + 8) * Dq + col;
            *(uint32_t*)&C[off0] = h2x(alpha * (acc[mt][nf][0] + vb.x),
                                       alpha * (acc[mt][nf][1] + vb.y));
            *(uint32_t*)&C[off1] = h2x(alpha * (acc[mt][nf][2] + vb.x),
                                       alpha * (acc[mt][nf][3] + vb.y));
        }
    }
}

// ---------------------------------------------------------------------------
// fp16 GEMM, fp32 output: out = ctx@Wo^T + bias. Same 256-thread shape.
// ---------------------------------------------------------------------------
__global__ __launch_bounds__(256, 2)
void gemm16_out_kernel(const __half* __restrict__ A, const __half* __restrict__ B,
                       const float* __restrict__ bias, float* __restrict__ C)
{
    extern __shared__ __half gsm[];
    const uint32_t sb = smem_u32(gsm);

    const int tid  = threadIdx.x;
    const int wid  = tid >> 5, lane = tid & 31;
    const int wm   = wid & 3,  wn   = wid >> 2;
    const int bm = blockIdx.y * 128, bn = blockIdx.x * 128;
    const int g_row = (lane & 7) + ((lane >> 3) & 1) * 8;
    const int g_col = ((lane >> 4) & 1) * 8;
    const int lrow0 = tid >> 3, lc16 = tid & 7;

    float acc[2][8][4];
    #pragma unroll
    for (int mt = 0; mt < 2; mt++)
        #pragma unroll
        for (int nf = 0; nf < 8; nf++)
            #pragma unroll
            for (int r = 0; r < 4; r++) acc[mt][nf][r] = 0.f;

    auto load_chunk = [&](int buf, int k0) {
        uint32_t base = sb + buf * 2 * TILEB;
        #pragma unroll
        for (int i = 0; i < 4; i++) {
            int row = lrow0 + i * 32;
            uint32_t so = (uint32_t)((row * GROW + lc16 * 8) * 2);
            cpa16(base + 0*TILEB + so, A + (size_t)(bm + row) * Dq + k0 + lc16 * 8);
            cpa16(base + 1*TILEB + so, B + (size_t)(bn + row) * Dq + k0 + lc16 * 8);
        }
        CPA_COMMIT();
    };

    load_chunk(0, 0);
    for (int kc = 0; kc < 16; kc++) {
        CPA_WAIT(0);
        __syncthreads();
        if (kc + 1 < 16) load_chunk((kc + 1) & 1, (kc + 1) * 64);

        uint32_t base = sb + (kc & 1) * 2 * TILEB;
        uint32_t uA = base, uB = base + TILEB;

        #pragma unroll
        for (int ks = 0; ks < 4; ks++) {
            const int kcol = ks * 16 + g_col;
            uint32_t av[2][4];
            #pragma unroll
            for (int mt = 0; mt < 2; mt++) {
                uint32_t off = ((wm*32 + mt*16 + g_row) * GROW + kcol) * 2;
                LDSM_X4(av[mt][0], av[mt][1], av[mt][2], av[mt][3], uA + off);
            }
            uint32_t bv[8][2];
            #pragma unroll
            for (int np = 0; np < 4; np++) {
                uint32_t off = ((wn*64 + np*16 + g_row) * GROW + kcol) * 2;
                uint32_t r0, r1, r2, r3;
                LDSM_X4(r0, r1, r2, r3, uB + off);
                bv[2*np][0] = r0;   bv[2*np][1] = r2;
                bv[2*np+1][0] = r1; bv[2*np+1][1] = r3;
            }
            #pragma unroll
            for (int mt = 0; mt < 2; mt++)
                #pragma unroll
                for (int nf = 0; nf < 8; nf++)
                    MMA16816F16(acc[mt][nf], av[mt], bv[nf]);
        }
    }

    const int qrow = lane >> 2, qcol = (lane & 3) * 2;
    #pragma unroll
    for (int mt = 0; mt < 2; mt++) {
        int r0 = bm + wm*32 + mt*16 + qrow;
        #pragma unroll
        for (int nf = 0; nf < 8; nf++) {
            int col = bn + wn*64 + nf*8 + qcol;
            float2 vb = *(const float2*)&bias[col];
            size_t off0 = (size_t)r0 * Dq + col;
            size_t off1 = (size_t)(r0 + 8) * Dq + col;
            *(float2*)&C[off0] = make_float2(acc[mt][nf][0] + vb.x, acc[mt][nf][1] + vb.y);
            *(float2*)&C[off1] = make_float2(acc[mt][nf][2] + vb.x, acc[mt][nf][3] + vb.y);
        }
    }
}

// ---------------------------------------------------------------------------
// Attention v10: single-pass flash, all-fp16 operands, fp32 accum.
// Stores UNNORMALIZED p = exp(s - m_chunk) during the loop; per-chunk maxima
// kept in small local arrays; final pass is a pure multiply (2 exps/chunk).
// Outer loop NOT unrolled (round-14 unroll caused I$/spill regression).
// smem tiles: 0 q, 1 k0, 2 v0, 3 k1, 4 v1 (+ mask)
// ---------------------------------------------------------------------------
#define ATS 72
#define ATILEB (128*ATS*2)
#define ATTN_SMEM (5*ATILEB + Tq*4)   // 96256

__global__ __launch_bounds__(256, 1)
void attn10_kernel(const __half* __restrict__ q_g, const __half* __restrict__ k_g,
                   const __half* __restrict__ v_g,
                   const int* __restrict__ mask, float* __restrict__ probs,
                   __half* __restrict__ ctx16)
{
    extern __shared__ __half sm_[];
    const uint32_t sb = smem_u32(sm_);
    int* msk = (int*)(sm_ + 5*128*ATS);

    const int t0 = blockIdx.x * 128, h = blockIdx.y, b = blockIdx.z;
    const int tid = threadIdx.x, wid = tid >> 5, lane = tid & 31;
    const int qrow = lane >> 2, qc2 = (lane & 3) * 2;
    const int g_row = (lane & 7) + ((lane >> 3) & 1) * 8;
    const int g_col = ((lane >> 4) & 1) * 8;
    const int lrow0 = tid >> 3, lc16 = tid & 7;

    const size_t gq  = ((size_t)(b*Tq + t0)) * Dq + h*DHq;
    const size_t gkv = ((size_t)(b*Tq)) * Dq + h*DHq;

    auto load_t = [&](int tile, const __half* src, size_t gbase) {
        #pragma unroll
        for (int i = 0; i < 4; i++) {
            int row = lrow0 + i*32;
            uint32_t so = (uint32_t)((row*ATS + lc16*8) * 2);
            cpa16(sb + tile*ATILEB + so, src + gbase + (size_t)row * Dq + lc16*8);
        }
    };

    load_t(0, q_g, gq);
    load_t(1, k_g, gkv);
    CPA_COMMIT();
    load_t(2, v_g, gkv);
    CPA_COMMIT();
    for (int s = tid; s < Tq; s += 256) msk[s] = mask[b*Tq + s];

    float m0 = -1e30f, m1 = -1e30f, l0 = 0.f, l1 = 0.f;
    float mh0[8], mh1[8];
    float cacc[8][4];
    #pragma unroll
    for (int nf = 0; nf < 8; nf++) {
        cacc[nf][0] = 0.f; cacc[nf][1] = 0.f; cacc[nf][2] = 0.f; cacc[nf][3] = 0.f;
    }

    const size_t prow0 = ((size_t)((b*Hq + h)*Tq) + t0 + wid*16 + qrow) * Tq;
    const uint32_t uq = sb;

    for (int st = 0; st < 8; st++) {          // rolled — do NOT unroll
        const int kb_ = 1 + (st & 1) * 2;
        const int vb_ = 2 + (st & 1) * 2;

        CPA_WAIT(1);
        __syncthreads();

        if (st < 7) {
            const int nk = 1 + ((st+1) & 1) * 2;
            const int nv = 2 + ((st+1) & 1) * 2;
            load_t(nk, k_g, gkv + (size_t)((st+1)*128) * Dq);
            CPA_COMMIT();
            load_t(nv, v_g, gkv + (size_t)((st+1)*128) * Dq);
            CPA_COMMIT();
        }

        // ---- S = q @ k^T : single-term fp16 ----
        float acc[16][4];
        #pragma unroll
        for (int nf = 0; nf < 16; nf++) {
            acc[nf][0] = 0.f; acc[nf][1] = 0.f; acc[nf][2] = 0.f; acc[nf][3] = 0.f;
        }
        {
            uint32_t uk = sb + kb_*ATILEB;
            #pragma unroll
            for (int ks = 0; ks < 4; ks++) {
                uint32_t aq[4];
                uint32_t aoff = (uint32_t)(((wid*16 + g_row) * ATS + ks*16 + g_col) * 2);
                LDSM_X4(aq[0], aq[1], aq[2], aq[3], uq + aoff);
                #pragma unroll
                for (int np = 0; np < 8; np++) {
                    uint32_t boff = (uint32_t)(((np*16 + g_row) * ATS + ks*16 + g_col) * 2);
                    uint32_t r0, r1, r2, r3;
                    LDSM_X4(r0, r1, r2, r3, uk + boff);
                    uint32_t b0[2] = {r0, r2}, b1[2] = {r1, r3};
                    MMA16816F16(acc[2*np],   aq, b0);
                    MMA16816F16(acc[2*np+1], aq, b1);
                }
            }
        }

        // ---- mask + online max ----
        int s0 = st * 128;
        float cm0 = -1e30f, cm1 = -1e30f;
        #pragma unroll
        for (int nf = 0; nf < 16; nf++) {
            int col = s0 + nf*8 + qc2;
            int k0 = msk[col], k1 = msk[col + 1];
            acc[nf][0] = k0 ? acc[nf][0] : -1e9f;
            acc[nf][1] = k1 ? acc[nf][1] : -1e9f;
            acc[nf][2] = k0 ? acc[nf][2] : -1e9f;
            acc[nf][3] = k1 ? acc[nf][3] : -1e9f;
            cm0 = fmaxf(cm0, fmaxf(acc[nf][0], acc[nf][1]));
            cm1 = fmaxf(cm1, fmaxf(acc[nf][2], acc[nf][3]));
        }
        cm0 = fmaxf(cm0, __shfl_xor_sync(0xffffffffu, cm0, 1));
        cm0 = fmaxf(cm0, __shfl_xor_sync(0xffffffffu, cm0, 2));
        cm1 = fmaxf(cm1, __shfl_xor_sync(0xffffffffu, cm1, 1));
        cm1 = fmaxf(cm1, __shfl_xor_sync(0xffffffffu, cm1, 2));
        float nm0 = fmaxf(m0, cm0), nm1 = fmaxf(m1, cm1);
        mh0[st] = nm0;  mh1[st] = nm1;
        float r0 = __expf(m0 - nm0), r1 = __expf(m1 - nm1);
        #pragma unroll
        for (int nf = 0; nf < 8; nf++) {
            cacc[nf][0] *= r0; cacc[nf][1] *= r0;
            cacc[nf][2] *= r1; cacc[nf][3] *= r1;
        }

        // ---- p = exp(s - nm): store unnormalized p + build fp16 P frags ----
        float sa0 = 0.f, sa1 = 0.f;
        uint32_t aP[8][4];
        #pragma unroll
        for (int j = 0; j < 8; j++) {
            float p[8];
            #pragma unroll
            for (int u = 0; u < 2; u++) {
                int nf = 2*j + u;
                int col = s0 + nf*8 + qc2;
                float p0 = __expf(acc[nf][0] - nm0);
                float p1 = __expf(acc[nf][1] - nm0);
                float p2 = __expf(acc[nf][2] - nm1);
                float p3 = __expf(acc[nf][3] - nm1);
                *(float2*)&probs[prow0 + col]        = make_float2(p0, p1);
                *(float2*)&probs[prow0 + 8*Tq + col] = make_float2(p2, p3);
                sa0 += p0 + p1;  sa1 += p2 + p3;
                p[u*4+0] = p0; p[u*4+1] = p1; p[u*4+2] = p2; p[u*4+3] = p3;
            }
            aP[j][0] = h2x(p[0], p[1]);
            aP[j][1] = h2x(p[2], p[3]);
            aP[j][2] = h2x(p[4], p[5]);
            aP[j][3] = h2x(p[6], p[7]);
        }
        sa0 += __shfl_xor_sync(0xffffffffu, sa0, 1);
        sa0 += __shfl_xor_sync(0xffffffffu, sa0, 2);
        sa1 += __shfl_xor_sync(0xffffffffu, sa1, 1);
        sa1 += __shfl_xor_sync(0xffffffffu, sa1, 2);
        l0 = l0 * r0 + sa0;  m0 = nm0;
        l1 = l1 * r1 + sa1;  m1 = nm1;

        if (st < 7) { CPA_WAIT(2); } else { CPA_WAIT(0); }
        __syncthreads();

        // ---- ctx += P @ V (fp16) ----
        uint32_t uv = sb + vb_*ATILEB;
        #pragma unroll
        for (int ks = 0; ks < 8; ks++) {
            uint32_t bv[8][2];
            #pragma unroll
            for (int npv = 0; npv < 4; npv++) {
                uint32_t off = (uint32_t)(((ks*16 + g_row) * ATS + npv*16 + g_col) * 2);
                uint32_t r0v, r1v, r2v, r3v;
                LDSM_T_X4(r0v, r1v, r2v, r3v, uv + off);
                bv[2*npv][0] = r0v;   bv[2*npv][1] = r1v;
                bv[2*npv+1][0] = r2v; bv[2*npv+1][1] = r3v;
            }
            #pragma unroll
            for (int nf = 0; nf < 8; nf++)
                MMA16816F16(cacc[nf], aP[ks], bv[nf]);
        }
    }

    const float iL0 = 1.0f / l0, iL1 = 1.0f / l1;

    // final pass: pure multiply p *= exp(mh[st]-M)*iL (2 exps per chunk)
    for (int st = 0; st < 8; st++) {          // rolled
        float sc0 = __expf(mh0[st] - m0) * iL0;
        float sc1 = __expf(mh1[st] - m1) * iL1;
        int s0 = st * 128;
        #pragma unroll
        for (int nf = 0; nf < 16; nf++) {
            int col = s0 + nf*8 + qc2;
            float2 v0 = *(float2*)&probs[prow0 + col];
            float2 v1 = *(float2*)&probs[prow0 + 8*Tq + col];
            v0.x *= sc0; v0.y *= sc0;
            v1.x *= sc1; v1.y *= sc1;
            *(float2*)&probs[prow0 + col]        = v0;
            *(float2*)&probs[prow0 + 8*Tq + col] = v1;
        }
    }

    // write ctx fp16
    {
        int r = t0 + wid*16 + qrow;
        size_t base0 = ((size_t)(b*Tq + r)) * Dq + h*DHq;
        size_t base1 = ((size_t)(b*Tq + r + 8)) * Dq + h*DHq;
        #pragma unroll
        for (int nf = 0; nf < 8; nf++) {
            int col = nf*8 + qc2;
            *(uint32_t*)&ctx16[base0 + col] = h2x(cacc[nf][0] * iL0, cacc[nf][1] * iL0);
            *(uint32_t*)&ctx16[base1 + col] = h2x(cacc[nf][2] * iL1, cacc[nf][3] * iL1);
        }
    }
}

// ---------------------------------------------------------------------------
extern "C" void kernel_launch(void* const* d_in, const int* in_sizes, int n_in,
                              void* d_out, int out_size)
{
    const float* query   = (const float*)d_in[0];
    const float* key     = (const float*)d_in[1];
    const float* value   = (const float*)d_in[2];
    const float* rel_pos = (const float*)d_in[3];
    const int*   kpm     = (const int*)  d_in[4];
    const float* qn_g = (const float*)d_in[5];
    const float* qn_b = (const float*)d_in[6];
    const float* kn_g = (const float*)d_in[7];
    const float* kn_b = (const float*)d_in[8];
    const float* vn_g = (const float*)d_in[9];
    const float* vn_b = (const float*)d_in[10];
    const float* Wq = (const float*)d_in[11];
    const float* bq = (const float*)d_in[12];
    const float* Wk = (const float*)d_in[13];
    const float* bk = (const float*)d_in[14];
    const float* Wv = (const float*)d_in[15];
    const float* bv = (const float*)d_in[16];
    const float* Wr = (const float*)d_in[17];
    const float* Wo = (const float*)d_in[18];
    const float* bo = (const float*)d_in[19];

    float* out   = (float*)d_out;
    float* probs = out + OUT_ELEMS;

    __half *lnq16,*lnk16,*lnv16,*rp16,*q16,*kr16,*v16,*ctx16;
    __half *wq16,*wk16,*wv16,*wr16,*wo16;
    cudaGetSymbolAddress((void**)&lnq16, g_lnq16);
    cudaGetSymbolAddress((void**)&lnk16, g_lnk16);
    cudaGetSymbolAddress((void**)&lnv16, g_lnv16);
    cudaGetSymbolAddress((void**)&rp16,  g_rp16);
    cudaGetSymbolAddress((void**)&q16,   g_q16);
    cudaGetSymbolAddress((void**)&kr16,  g_kr16);
    cudaGetSymbolAddress((void**)&v16,   g_v16);
    cudaGetSymbolAddress((void**)&ctx16, g_ctx16);
    cudaGetSymbolAddress((void**)&wq16, g_wq16);
    cudaGetSymbolAddress((void**)&wk16, g_wk16);
    cudaGetSymbolAddress((void**)&wv16, g_wv16);
    cudaGetSymbolAddress((void**)&wr16, g_wr16);
    cudaGetSymbolAddress((void**)&wo16, g_wo16);

    cudaFuncSetAttribute(proj16_kernel, cudaFuncAttributeMaxDynamicSharedMemorySize, G16_BYTES);
    cudaFuncSetAttribute(gemm16_out_kernel, cudaFuncAttributeMaxDynamicSharedMemorySize, G16_BYTES);
    cudaFuncSetAttribute(attn10_kernel, cudaFuncAttributeMaxDynamicSharedMemorySize, ATTN_SMEM);

    // 1) weight transpose -> fp16 (0.1 folded into Wr)
    WSplitArgs wa;
    wa.W[0]=Wq; wa.H[0]=wq16; wa.scale[0]=1.f;
    wa.W[1]=Wk; wa.H[1]=wk16; wa.scale[1]=1.f;
    wa.W[2]=Wv; wa.H[2]=wv16; wa.scale[2]=1.f;
    wa.W[3]=Wr; wa.H[3]=wr16; wa.scale[3]=0.1f;
    wa.W[4]=Wo; wa.H[4]=wo16; wa.scale[4]=1.f;
    dim3 wgrid(Dq/32, Dq/32, 5);
    wsplit5_kernel<<<wgrid, 256>>>(wa);

    // 2) LayerNorms -> fp16, rel_pos -> fp16
    LnArgs la;
    la.x[0]=query; la.g[0]=qn_g; la.b[0]=qn_b; la.o[0]=lnq16;
    la.x[1]=key;   la.g[1]=kn_g; la.b[1]=kn_b; la.o[1]=lnk16;
    la.x[2]=value; la.g[2]=vn_g; la.b[2]=vn_b; la.o[2]=lnv16;
    ln3_kernel<<<dim3(Mrows, 3), 256>>>(la);
    f16cvt_kernel<<<(Mrows*Dq)/1024, 256>>>(rel_pos, rp16);

    // 3) merged fp16 projections: q, v, kr=[lnk|rp]@[Wk;0.1Wr]
    Proj16Args pa;
    pa.A[0]=lnq16; pa.B[0]=wq16; pa.bias[0]=bq; pa.alpha[0]=0.125f;
    pa.C[0]=q16;  pa.nch[0]=16;
    pa.A[1]=lnv16; pa.B[1]=wv16; pa.bias[1]=bv; pa.alpha[1]=1.f;
    pa.C[1]=v16;  pa.nch[1]=16;
    pa.A[2]=lnk16; pa.B[2]=wk16; pa.bias[2]=bk; pa.alpha[2]=1.f;
    pa.A2=rp16; pa.B2=wr16;
    pa.C[2]=kr16; pa.nch[2]=32;
    proj16_kernel<<<dim3(Dq/128, 96), 256, G16_BYTES>>>(pa);

    // 4) single-pass flash attention -> unnormalized p + final rescale + ctx
    dim3 agrid(Tq/128, Hq, Bq);
    attn10_kernel<<<agrid, 256, ATTN_SMEM>>>(q16, kr16, v16, kpm, probs, ctx16);

    // 5) out = ctx@Wo + bo
    gemm16_out_kernel<<<dim3(Dq/128, Mrows/128), 256, G16_BYTES>>>(
        ctx16, wo16, bo, out);
}